// round 13
// baseline (speedup 1.0000x reference)
#include <cuda_runtime.h>
#include <cuda_bf16.h>
#include <cstdint>

// ---------------- problem constants ----------------
#define BSZ 2
#define TLEN 1024
#define HID 2048
#define NHEADS 2
#define HH 6
#define DK 256
#define DV 512
#define KEY_DIM 1536   // HH*DK
#define VAL_DIM 3072   // HH*DV
#define RROWS 2048     // BSZ*TLEN

// concatenated projection layout: [ q | k0 | k1 | v0 | v1 | gate ]
#define PROJ_W 13824
#define OFF_Q  0
#define OFF_K0 1536
#define OFF_K1 3072
#define OFF_V0 4608
#define OFF_V1 7680
#define OFF_G  10752

// ---------------- scratch (static device memory; no allocs) ----------------
__device__ float g_proj[(size_t)RROWS * PROJ_W];
__device__ __nv_bfloat16 g_xhi[(size_t)RROWS * HID];
__device__ __nv_bfloat16 g_xlo[(size_t)RROWS * HID];
__device__ __nv_bfloat16 g_wch[(size_t)HID * PROJ_W];
__device__ __nv_bfloat16 g_wcl[(size_t)HID * PROJ_W];
__device__ __nv_bfloat16 g_owh[(size_t)VAL_DIM * HID];
__device__ __nv_bfloat16 g_owl[(size_t)VAL_DIM * HID];
__device__ __nv_bfloat16 g_ybh[(size_t)RROWS * VAL_DIM];
__device__ __nv_bfloat16 g_ybl[(size_t)RROWS * VAL_DIM];
__device__ float g_qn [RROWS*KEY_DIM];
__device__ float g_kn0[RROWS*KEY_DIM];
__device__ float g_kn1[RROWS*KEY_DIM];
__device__ float g_vs0[RROWS*VAL_DIM];
__device__ float g_vs1[RROWS*VAL_DIM];
__device__ float g_ob [RROWS*VAL_DIM];
__device__ float g_be0[RROWS*HH];
__device__ float g_be1[RROWS*HH];
__device__ float g_gd [RROWS*HH];

// ================= helpers =================
__device__ __forceinline__ uint32_t smem_u32(const void* p) {
    uint32_t a;
    asm("{ .reg .u64 t; cvta.to.shared.u64 t, %1; cvt.u32.u64 %0, t; }" : "=r"(a) : "l"(p));
    return a;
}
__device__ __forceinline__ void ldmx4(uint32_t* r, uint32_t addr) {
    asm volatile("ldmatrix.sync.aligned.m8n8.x4.shared.b16 {%0,%1,%2,%3}, [%4];"
        : "=r"(r[0]), "=r"(r[1]), "=r"(r[2]), "=r"(r[3]) : "r"(addr));
}
__device__ __forceinline__ void ldmx2t(uint32_t* r, uint32_t addr) {
    asm volatile("ldmatrix.sync.aligned.m8n8.x2.trans.shared.b16 {%0,%1}, [%2];"
        : "=r"(r[0]), "=r"(r[1]) : "r"(addr));
}
__device__ __forceinline__ void mma16816(float* c, const uint32_t* a, const uint32_t* b) {
    asm volatile(
        "mma.sync.aligned.m16n8k16.row.col.f32.bf16.bf16.f32 "
        "{%0,%1,%2,%3}, {%4,%5,%6,%7}, {%8,%9}, {%0,%1,%2,%3};"
        : "+f"(c[0]), "+f"(c[1]), "+f"(c[2]), "+f"(c[3])
        : "r"(a[0]), "r"(a[1]), "r"(a[2]), "r"(a[3]), "r"(b[0]), "r"(b[1]));
}
__device__ __forceinline__ void cpa16(uint32_t dst, const void* src) {
    asm volatile("cp.async.cg.shared.global [%0], [%1], 16;" :: "r"(dst), "l"(src));
}

__device__ __forceinline__ void split_write(
    float4 v, __nv_bfloat16* __restrict__ h, __nv_bfloat16* __restrict__ l, size_t d)
{
    __nv_bfloat162 h0 = __floats2bfloat162_rn(v.x, v.y);
    __nv_bfloat162 h1 = __floats2bfloat162_rn(v.z, v.w);
    __nv_bfloat162 l0 = __floats2bfloat162_rn(v.x - __low2float(h0), v.y - __high2float(h0));
    __nv_bfloat162 l1 = __floats2bfloat162_rn(v.z - __low2float(h1), v.w - __high2float(h1));
    *reinterpret_cast<__nv_bfloat162*>(h + d)     = h0;
    *reinterpret_cast<__nv_bfloat162*>(h + d + 2) = h1;
    *reinterpret_cast<__nv_bfloat162*>(l + d)     = l0;
    *reinterpret_cast<__nv_bfloat162*>(l + d + 2) = l1;
}

// ================= MEGA pre-pass: x split + all weight splits + 18-wide projections =================
// block ranges (256 threads each):
//   [0, 4096)            : x -> xhi/xlo
//   [4096, 37888)        : weights -> wch/wcl (concatenated) and o_w -> owh/owl
//   [37888, 38912)       : gemm18 (2 rows per block) + activations
#define XS_BLOCKS 4096
#define W_BLOCKS  33792
#define G_BLOCKS  1024
#define MEGA_BLOCKS (XS_BLOCKS + W_BLOCKS + G_BLOCKS)

__global__ __launch_bounds__(256) void cvt_mega(
    const float* __restrict__ x,
    const float* __restrict__ q_w, const float* __restrict__ k_ws,
    const float* __restrict__ v_ws, const float* __restrict__ g_w,
    const float* __restrict__ o_w,
    const float* __restrict__ b_ws, const float* __restrict__ a_w,
    const float* __restrict__ A_log, const float* __restrict__ dtb,
    __nv_bfloat16* __restrict__ xhi, __nv_bfloat16* __restrict__ xlo,
    __nv_bfloat16* __restrict__ wch, __nv_bfloat16* __restrict__ wcl,
    __nv_bfloat16* __restrict__ owh, __nv_bfloat16* __restrict__ owl,
    float* __restrict__ be0, float* __restrict__ be1, float* __restrict__ gd)
{
    const int bid = blockIdx.x, tid = threadIdx.x;
    __shared__ float red[256 * 40];

    if (bid < XS_BLOCKS) {
        int i = (bid * 256 + tid) * 4;
        split_write(*reinterpret_cast<const float4*>(x + i), xhi, xlo, (size_t)i);
        return;
    }
    if (bid < XS_BLOCKS + W_BLOCKS) {
        int qd = (bid - XS_BLOCKS) * 256 + tid;   // quad index
        const float* s;
        int Ns, off;
        if (qd < 2359296) {
            int seg = qd / 786432;
            qd -= seg * 786432;
            s = (seg == 0) ? q_w : k_ws + (size_t)(seg - 1) * ((size_t)HID * KEY_DIM);
            Ns = KEY_DIM; off = seg * KEY_DIM;
        } else if (qd < 7077888) {
            int qq = qd - 2359296;
            int seg = qq / 1572864;
            qd = qq - seg * 1572864;
            s = (seg == 2) ? g_w : v_ws + (size_t)seg * ((size_t)HID * VAL_DIM);
            Ns = VAL_DIM; off = OFF_V0 + seg * VAL_DIM;
        } else {
            int i = (qd - 7077888) * 4;
            split_write(*reinterpret_cast<const float4*>(o_w + i), owh, owl, (size_t)i);
            return;
        }
        int i = qd * 4;
        int k = i / Ns, n = i - k * Ns;
        size_t d = (size_t)k * PROJ_W + off + n;
        split_write(*reinterpret_cast<const float4*>(s + i), wch, wcl, d);
        return;
    }

    // ---- gemm18 segment: 2 rows per block; thread owns contiguous k in [tid*8, tid*8+8) ----
    const int r0 = (bid - XS_BLOCKS - W_BLOCKS) * 2;
    const int k0 = tid * 8;
    float acc[2][18];
#pragma unroll
    for (int rr = 0; rr < 2; rr++)
#pragma unroll
        for (int j = 0; j < 18; j++) acc[rr][j] = 0.f;

    float xa[2][8];
    {
        const float* a0 = x + (size_t)r0 * HID + k0;
        const float* a1 = a0 + HID;
#pragma unroll
        for (int q = 0; q < 2; q++) {
            float4 v0 = *reinterpret_cast<const float4*>(a0 + q * 4);
            float4 v1 = *reinterpret_cast<const float4*>(a1 + q * 4);
            xa[0][q*4+0]=v0.x; xa[0][q*4+1]=v0.y; xa[0][q*4+2]=v0.z; xa[0][q*4+3]=v0.w;
            xa[1][q*4+0]=v1.x; xa[1][q*4+1]=v1.y; xa[1][q*4+2]=v1.z; xa[1][q*4+3]=v1.w;
        }
    }

    const float* wp[3];
    wp[0] = b_ws + (size_t)k0 * 6;
    wp[1] = b_ws + (size_t)HID * 6 + (size_t)k0 * 6;
    wp[2] = a_w + (size_t)k0 * 6;
#pragma unroll
    for (int m = 0; m < 3; m++) {
        const float* w = wp[m];
#pragma unroll
        for (int kk = 0; kk < 8; kk += 2) {
            float4 w0 = *reinterpret_cast<const float4*>(w + kk * 6);
            float4 w1 = *reinterpret_cast<const float4*>(w + kk * 6 + 4);
            float4 w2 = *reinterpret_cast<const float4*>(w + kk * 6 + 8);
            float wv[12] = {w0.x,w0.y,w0.z,w0.w, w1.x,w1.y,w1.z,w1.w, w2.x,w2.y,w2.z,w2.w};
#pragma unroll
            for (int rr = 0; rr < 2; rr++) {
                float aA = xa[rr][kk], aB = xa[rr][kk + 1];
#pragma unroll
                for (int j = 0; j < 6; j++) {
                    acc[rr][m*6+j] = fmaf(aA, wv[j],     acc[rr][m*6+j]);
                    acc[rr][m*6+j] = fmaf(aB, wv[6 + j], acc[rr][m*6+j]);
                }
            }
        }
    }
#pragma unroll
    for (int rr = 0; rr < 2; rr++)
#pragma unroll
        for (int j = 0; j < 18; j++) red[tid * 40 + rr * 20 + j] = acc[rr][j];
    __syncthreads();
    for (int s = 128; s > 0; s >>= 1) {
        if (tid < s) {
#pragma unroll
            for (int j = 0; j < 40; j++) red[tid * 40 + j] += red[(tid + s) * 40 + j];
        }
        __syncthreads();
    }
    if (tid < 36) {
        int rr = tid / 18, u = tid % 18;
        float v = red[rr * 20 + u];
        int r = r0 + rr;
        int j = u % 6;
        if (u < 6) {
            be0[r * 6 + j] = 1.f / (1.f + expf(-v));
        } else if (u < 12) {
            be1[r * 6 + j] = 1.f / (1.f + expf(-v));
        } else {
            float z = v + dtb[j];
            float sp = (z > 20.f) ? z : log1pf(expf(z));
            gd[r * 6 + j] = -expf(A_log[j]) * sp;
        }
    }
}

// ================= bf16x3 HMMA GEMM, 3-stage cp.async =================
// Tile 128x128, BK=32, 256 threads, 2 CTAs/SM, 3-stage pipeline.
// Stage: Ahi[128x80B]=10240 | Alo=10240 | Bhi[32x256B]=8192 | Blo=8192 = 36864
#define HSTG 36864
#define HSM3 (3 * HSTG)

__device__ __forceinline__ void issue_stage(
    uint32_t st,
    const __nv_bfloat16* __restrict__ Ahi, const __nv_bfloat16* __restrict__ Alo,
    const __nv_bfloat16* __restrict__ Bhi, const __nv_bfloat16* __restrict__ Blo,
    int bm, int bn, int kt, int N, int K, int tid)
{
#pragma unroll
    for (int hq = 0; hq < 2; hq++) {
        int c = tid + hq * 256;
        int m = c >> 2, sl = c & 3;
        size_t so = (size_t)(bm + m) * K + kt + sl * 8;
        uint32_t d = st + m * 80 + sl * 16;
        cpa16(d,          Ahi + so);
        cpa16(d + 10240,  Alo + so);
    }
#pragma unroll
    for (int hq = 0; hq < 2; hq++) {
        int c = tid + hq * 256;
        int k = c >> 4, n8 = c & 15;
        size_t so = (size_t)(kt + k) * N + bn + n8 * 8;
        uint32_t sw = (uint32_t)(((n8 & 8) | ((n8 ^ k) & 7)) * 16);
        uint32_t d = st + 20480 + k * 256 + sw;
        cpa16(d,         Bhi + so);
        cpa16(d + 8192,  Blo + so);
    }
}

__global__ void __launch_bounds__(256, 2) hgemm2(
    const __nv_bfloat16* __restrict__ Ahi, const __nv_bfloat16* __restrict__ Alo,
    const __nv_bfloat16* __restrict__ Bhi, const __nv_bfloat16* __restrict__ Blo,
    float* __restrict__ C, int M, int N, int K)
{
    extern __shared__ char sm2[];
    const uint32_t sbase = smem_u32(sm2);
    const int tid = threadIdx.x, lane = tid & 31, w = tid >> 5;
    const int wm = (w >> 2) * 64, wn = (w & 3) * 32;
    const int bm = blockIdx.y * 128, bn = blockIdx.x * 128;
    const int wslot = (w & 3) * 4;

    float acc[4][4][4];
#pragma unroll
    for (int i = 0; i < 4; i++)
#pragma unroll
        for (int j = 0; j < 4; j++)
#pragma unroll
            for (int q = 0; q < 4; q++) acc[i][j][q] = 0.f;

    const int niter = K >> 5;
    const uint32_t a_lane = (uint32_t)((wm + (lane & 15)) * 80 + ((lane >> 4) << 4));

    issue_stage(sbase,        Ahi, Alo, Bhi, Blo, bm, bn, 0,  N, K, tid);
    asm volatile("cp.async.commit_group;" ::: "memory");
    issue_stage(sbase + HSTG, Ahi, Alo, Bhi, Blo, bm, bn, 32, N, K, tid);
    asm volatile("cp.async.commit_group;" ::: "memory");

    int cbuf = 0;
    int ibuf = 2;
    for (int it = 0; it < niter; ++it) {
        if (it + 2 < niter) {
            issue_stage(sbase + (uint32_t)ibuf * HSTG,
                        Ahi, Alo, Bhi, Blo, bm, bn, (it + 2) << 5, N, K, tid);
            asm volatile("cp.async.commit_group;" ::: "memory");
            asm volatile("cp.async.wait_group 2;" ::: "memory");
            if (++ibuf == 3) ibuf = 0;
        } else if (it + 1 < niter) {
            asm volatile("cp.async.wait_group 1;" ::: "memory");
        } else {
            asm volatile("cp.async.wait_group 0;" ::: "memory");
        }
        __syncthreads();

        const uint32_t sA   = sbase + (uint32_t)cbuf * HSTG;
        const uint32_t sAlo = sA + 10240;
        const uint32_t sB   = sA + 20480;
        const uint32_t sBlo = sB + 8192;

#pragma unroll
        for (int ks = 0; ks < 32; ks += 16) {
            const int klane = ks + (lane & 15);
            const uint32_t bro = (uint32_t)(klane * 256);
            uint32_t bh[4][2], bl[4][2];
#pragma unroll
            for (int ni = 0; ni < 4; ni++) {
                const int slot = wslot + ni;
                const uint32_t off = bro + (uint32_t)((((slot ^ klane) & 7) | (slot & 8)) * 16);
                ldmx2t(bh[ni], sB + off);
                ldmx2t(bl[ni], sBlo + off);
            }
            const uint32_t ao = a_lane + ks * 2;
#pragma unroll
            for (int mi = 0; mi < 4; mi++) {
                uint32_t ah[4], al_[4];
                ldmx4(ah,  sA   + ao + mi * (16 * 80));
                ldmx4(al_, sAlo + ao + mi * (16 * 80));
#pragma unroll
                for (int ni = 0; ni < 4; ni++) {
                    mma16816(acc[mi][ni], ah,  bh[ni]);
                    mma16816(acc[mi][ni], al_, bh[ni]);
                    mma16816(acc[mi][ni], ah,  bl[ni]);
                }
            }
        }
        __syncthreads();
        if (++cbuf == 3) cbuf = 0;
    }

    // epilogue
#pragma unroll
    for (int mi = 0; mi < 4; mi++) {
        const int row = bm + wm + mi * 16 + (lane >> 2);
#pragma unroll
        for (int ni = 0; ni < 4; ni++) {
            const int col = bn + wn + ni * 8 + (lane & 3) * 2;
            float2 v0; v0.x = acc[mi][ni][0]; v0.y = acc[mi][ni][1];
            float2 v1; v1.x = acc[mi][ni][2]; v1.y = acc[mi][ni][3];
            *reinterpret_cast<float2*>(C + (size_t)row * N + col)       = v0;
            *reinterpret_cast<float2*>(C + (size_t)(row + 8) * N + col) = v1;
        }
    }
}

// ================= ALL convolutions in ONE launch =================
#define CONV_QK_BLOCKS (RROWS * 18)
#define CONV_V_BLOCKS  ((RROWS * VAL_DIM * 2) / 256)
__global__ __launch_bounds__(256) void conv_all(
    const float* __restrict__ Z, const float* __restrict__ qcw,
    const float* __restrict__ kcw, const float* __restrict__ vcw,
    float* __restrict__ qn, float* __restrict__ kn0, float* __restrict__ kn1,
    float* __restrict__ vs0, float* __restrict__ vs1)
{
    const int bid = blockIdx.x, tid = threadIdx.x;
    if (bid < CONV_QK_BLOCKS) {
        const int r = bid / 18, u = bid - (bid / 18) * 18;
        const int tsel = u / 6, h = u - tsel * 6;
        const int zoff = tsel * KEY_DIM;
        const float* W = (tsel == 0) ? qcw : kcw + (size_t)(tsel - 1) * (KEY_DIM * 4);
        const float outscale = (tsel == 0) ? 0.0625f : 1.f;
        float* Out = (tsel == 0) ? qn : ((tsel == 1) ? kn0 : kn1);

        const int b = r >> 10, t = r & 1023;
        const int c = h * DK + tid;
        float acc = 0.f;
#pragma unroll
        for (int j = 0; j < 4; j++) {
            int tj = t - 3 + j;
            if (tj >= 0) acc = fmaf(Z[(size_t)(b * TLEN + tj) * PROJ_W + zoff + c], W[c * 4 + j], acc);
        }
        float y = acc / (1.f + expf(-acc));
        __shared__ float sred[256];
        sred[tid] = y * y;
        __syncthreads();
        for (int s = 128; s > 0; s >>= 1) {
            if (tid < s) sred[tid] += sred[tid + s];
            __syncthreads();
        }
        float scale = rsqrtf(sred[0] + 1e-12f) * outscale;
        Out[(size_t)r * KEY_DIM + c] = y * scale;
    } else {
        int idx = (bid - CONV_QK_BLOCKS) * 256 + tid;
        const int vsel = (idx >= RROWS * VAL_DIM) ? 1 : 0;
        idx -= vsel * (RROWS * VAL_DIM);
        const int zoff = OFF_V0 + vsel * VAL_DIM;
        const float* W = vcw + (size_t)vsel * (VAL_DIM * 4);
        float* Out = vsel ? vs1 : vs0;

        const int c = idx % VAL_DIM;
        const int r = idx / VAL_DIM;
        const int b = r >> 10, t = r & 1023;
        float acc = 0.f;
#pragma unroll
        for (int j = 0; j < 4; j++) {
            int tj = t - 3 + j;
            if (tj >= 0) acc = fmaf(Z[(size_t)(b * TLEN + tj) * PROJ_W + zoff + c], W[c * 4 + j], acc);
        }
        Out[idx] = acc / (1.f + expf(-acc));
    }
}

// ---------------- packed f32x2 helpers ----------------
union F2U { float2 f; unsigned long long u; };

__device__ __forceinline__ F2U ffma2(F2U a, F2U b, F2U c) {
    F2U r;
    asm("fma.rn.f32x2 %0, %1, %2, %3;" : "=l"(r.u) : "l"(a.u), "l"(b.u), "l"(c.u));
    return r;
}
__device__ __forceinline__ F2U fmul2(F2U a, F2U b) {
    F2U r;
    asm("mul.rn.f32x2 %0, %1, %2;" : "=l"(r.u) : "l"(a.u), "l"(b.u));
    return r;
}

// ---------------- gated delta-rule recurrence v2 ----------------
__global__ void __launch_bounds__(128, 3) delta_recur2(
    const float* __restrict__ Qn,  const float* __restrict__ Kn0, const float* __restrict__ Kn1,
    const float* __restrict__ Vs0, const float* __restrict__ Vs1,
    const float* __restrict__ Be0, const float* __restrict__ Be1,
    const float* __restrict__ Gd,  float* __restrict__ O)
{
    const int bh = blockIdx.x;
    const int b = bh / HH, h = bh % HH;
    const int tid = threadIdx.x;
    const int w = tid >> 5, lane = tid & 31;
    const int half = lane >> 4, l0 = lane & 15;
    const int col0 = blockIdx.y * 16 + w * 4 + half * 2;

    __shared__ __align__(16) float sk[3][3][256];

    F2U S0[8], S1[8];
#pragma unroll
    for (int j = 0; j < 8; j++) { S0[j].u = 0ull; S1[j].u = 0ull; }

    {
        const size_t kb = (size_t)(b * TLEN) * KEY_DIM + h * DK + tid * 2;
        *reinterpret_cast<float2*>(&sk[0][0][tid * 2]) = *reinterpret_cast<const float2*>(Kn0 + kb);
        *reinterpret_cast<float2*>(&sk[0][1][tid * 2]) = *reinterpret_cast<const float2*>(Kn1 + kb);
        *reinterpret_cast<float2*>(&sk[0][2][tid * 2]) = *reinterpret_cast<const float2*>(Qn + kb);
    }
    const size_t vb0 = (size_t)(b * TLEN) * VAL_DIM + h * DV + col0;
    float2 vc0 = *reinterpret_cast<const float2*>(Vs0 + vb0);
    float2 vc1 = *reinterpret_cast<const float2*>(Vs1 + vb0);
    const int gi0 = (b * TLEN) * HH + h;
    float gcur = Gd[gi0], b0cur = Be0[gi0], b1cur = Be1[gi0];
    __syncthreads();

    int cur = 0;
    for (int t = 0; t < TLEN; t++) {
        const int nxt = (cur == 2) ? 0 : cur + 1;
        const int r = b * TLEN + t;
        const bool more = (t + 1 < TLEN);

        float2 kr0, kr1, krq, vn0, vn1;
        float gn = 0.f, bn0 = 0.f, bn1 = 0.f;
        if (more) {
            const size_t kb = (size_t)(r + 1) * KEY_DIM + h * DK + tid * 2;
            kr0 = *reinterpret_cast<const float2*>(Kn0 + kb);
            kr1 = *reinterpret_cast<const float2*>(Kn1 + kb);
            krq = *reinterpret_cast<const float2*>(Qn + kb);
            const size_t vb = (size_t)(r + 1) * VAL_DIM + h * DV + col0;
            vn0 = *reinterpret_cast<const float2*>(Vs0 + vb);
            vn1 = *reinterpret_cast<const float2*>(Vs1 + vb);
            const int gi = (r + 1) * HH + h;
            gn = Gd[gi]; bn0 = Be0[gi]; bn1 = Be1[gi];
        }

        const float decay = expf(gcur);
        const float2* pk0 = reinterpret_cast<const float2*>(sk[cur][0]);
        const float2* pk1 = reinterpret_cast<const float2*>(sk[cur][1]);
        const float2* pq  = reinterpret_cast<const float2*>(sk[cur][2]);

        F2U rk[8];
        // ---- pass 0: k0 ----
#pragma unroll
        for (int j = 0; j < 8; j++) rk[j].f = pk0[j * 16 + l0];
        F2U aA, aB; aA.u = 0ull; aB.u = 0ull;
#pragma unroll
        for (int j = 0; j < 8; j++) { aA = ffma2(rk[j], S0[j], aA); aB = ffma2(rk[j], S1[j], aB); }
        float dA = aA.f.x + aA.f.y, dB = aB.f.x + aB.f.y;
#pragma unroll
        for (int m = 8; m > 0; m >>= 1) {
            dA += __shfl_xor_sync(0xffffffffu, dA, m);
            dB += __shfl_xor_sync(0xffffffffu, dB, m);
        }
        dA *= decay; dB *= decay;
        const float u0A = (vc0.x - dA) * b0cur, u0B = (vc0.y - dB) * b0cur;
        F2U dec2; dec2.f = make_float2(decay, decay);
        F2U uA; uA.f = make_float2(u0A, u0A);
        F2U uB; uB.f = make_float2(u0B, u0B);
#pragma unroll
        for (int j = 0; j < 8; j++) {
            S0[j] = ffma2(S0[j], dec2, fmul2(rk[j], uA));
            S1[j] = ffma2(S1[j], dec2, fmul2(rk[j], uB));
        }
        // ---- pass 1: k1 ----
#pragma unroll
        for (int j = 0; j < 8; j++) rk[j].f = pk1[j * 16 + l0];
        aA.u = 0ull; aB.u = 0ull;
#pragma unroll
        for (int j = 0; j < 8; j++) { aA = ffma2(rk[j], S0[j], aA); aB = ffma2(rk[j], S1[j], aB); }
        dA = aA.f.x + aA.f.y; dB = aB.f.x + aB.f.y;
#pragma unroll
        for (int m = 8; m > 0; m >>= 1) {
            dA += __shfl_xor_sync(0xffffffffu, dA, m);
            dB += __shfl_xor_sync(0xffffffffu, dB, m);
        }
        const float u1A = (vc1.x - dA) * b1cur, u1B = (vc1.y - dB) * b1cur;
        uA.f = make_float2(u1A, u1A); uB.f = make_float2(u1B, u1B);
#pragma unroll
        for (int j = 0; j < 8; j++) {
            S0[j] = ffma2(rk[j], uA, S0[j]);
            S1[j] = ffma2(rk[j], uB, S1[j]);
        }
        // ---- readout: q ----
#pragma unroll
        for (int j = 0; j < 8; j++) rk[j].f = pq[j * 16 + l0];
        aA.u = 0ull; aB.u = 0ull;
#pragma unroll
        for (int j = 0; j < 8; j++) { aA = ffma2(rk[j], S0[j], aA); aB = ffma2(rk[j], S1[j], aB); }
        dA = aA.f.x + aA.f.y; dB = aB.f.x + aB.f.y;
#pragma unroll
        for (int m = 8; m > 0; m >>= 1) {
            dA += __shfl_xor_sync(0xffffffffu, dA, m);
            dB += __shfl_xor_sync(0xffffffffu, dB, m);
        }
        if (l0 == 0) {
            float2 ov; ov.x = dA; ov.y = dB;
            *reinterpret_cast<float2*>(O + (size_t)(r * HH + h) * DV + col0) = ov;
        }

        if (more) {
            *reinterpret_cast<float2*>(&sk[nxt][0][tid * 2]) = kr0;
            *reinterpret_cast<float2*>(&sk[nxt][1][tid * 2]) = kr1;
            *reinterpret_cast<float2*>(&sk[nxt][2][tid * 2]) = krq;
            vc0 = vn0; vc1 = vn1; gcur = gn; b0cur = bn0; b1cur = bn1;
            __syncthreads();
        }
        cur = nxt;
    }
}

// ---------------- RMS norm over DV + gated SiLU -> bf16 hi/lo ----------------
__global__ __launch_bounds__(256) void rms_gate(
    const float* __restrict__ Ob, const float* __restrict__ Gx,
    const float* __restrict__ onw,
    __nv_bfloat16* __restrict__ Yh, __nv_bfloat16* __restrict__ Yl)
{
    const int r = blockIdx.x, h = blockIdx.y, tid = threadIdx.x;
    const size_t base = (size_t)(r * HH + h) * DV;
    const size_t gbase = (size_t)r * PROJ_W + OFF_G + h * DV;
    float o0 = Ob[base + tid], o1 = Ob[base + tid + 256];
    __shared__ float sred[256];
    sred[tid] = o0 * o0 + o1 * o1;
    __syncthreads();
    for (int s = 128; s > 0; s >>= 1) {
        if (tid < s) sred[tid] += sred[tid + s];
        __syncthreads();
    }
    float scale = rsqrtf(sred[0] * (1.f / 512.f) + 1e-5f);
    float g0 = Gx[gbase + tid], g1 = Gx[gbase + tid + 256];
    float y0 = o0 * scale * onw[tid]       * (g0 / (1.f + expf(-g0)));
    float y1 = o1 * scale * onw[tid + 256] * (g1 / (1.f + expf(-g1)));
    __nv_bfloat16 h0 = __float2bfloat16_rn(y0);
    __nv_bfloat16 h1 = __float2bfloat16_rn(y1);
    Yh[base + tid]       = h0;
    Yh[base + tid + 256] = h1;
    Yl[base + tid]       = __float2bfloat16_rn(y0 - __bfloat162float(h0));
    Yl[base + tid + 256] = __float2bfloat16_rn(y1 - __bfloat162float(h1));
}

// ---------------- launch ----------------
extern "C" void kernel_launch(void* const* d_in, const int* in_sizes, int n_in,
                              void* d_out, int out_size)
{
    const float* x     = (const float*)d_in[0];
    const float* q_w   = (const float*)d_in[1];
    const float* k_ws  = (const float*)d_in[2];
    const float* v_ws  = (const float*)d_in[3];
    const float* b_ws  = (const float*)d_in[4];
    const float* a_w   = (const float*)d_in[5];
    const float* g_w   = (const float*)d_in[6];
    const float* o_w   = (const float*)d_in[7];
    const float* qcw   = (const float*)d_in[8];
    const float* kcw   = (const float*)d_in[9];
    const float* vcw   = (const float*)d_in[10];
    const float* A_log = (const float*)d_in[11];
    const float* dtb   = (const float*)d_in[12];
    const float* onw   = (const float*)d_in[13];
    float* out = (float*)d_out;

    float *proj, *qn, *kn0, *kn1, *vs0, *vs1, *ob;
    float *be0, *be1, *gd;
    __nv_bfloat16 *xhi, *xlo, *wch, *wcl, *owh, *owl, *ybh, *ybl;
    cudaGetSymbolAddress((void**)&proj, g_proj);
    cudaGetSymbolAddress((void**)&xhi, g_xhi);
    cudaGetSymbolAddress((void**)&xlo, g_xlo);
    cudaGetSymbolAddress((void**)&wch, g_wch);
    cudaGetSymbolAddress((void**)&wcl, g_wcl);
    cudaGetSymbolAddress((void**)&owh, g_owh);
    cudaGetSymbolAddress((void**)&owl, g_owl);
    cudaGetSymbolAddress((void**)&ybh, g_ybh);
    cudaGetSymbolAddress((void**)&ybl, g_ybl);
    cudaGetSymbolAddress((void**)&qn,  g_qn);
    cudaGetSymbolAddress((void**)&kn0, g_kn0);
    cudaGetSymbolAddress((void**)&kn1, g_kn1);
    cudaGetSymbolAddress((void**)&vs0, g_vs0);
    cudaGetSymbolAddress((void**)&vs1, g_vs1);
    cudaGetSymbolAddress((void**)&ob,  g_ob);
    cudaGetSymbolAddress((void**)&be0, g_be0);
    cudaGetSymbolAddress((void**)&be1, g_be1);
    cudaGetSymbolAddress((void**)&gd,  g_gd);

    cudaFuncSetAttribute(hgemm2, cudaFuncAttributeMaxDynamicSharedMemorySize, HSM3);

    // 1) mega pre-pass: x split + weight splits + tiny projections/activations
    cvt_mega<<<MEGA_BLOCKS, 256>>>(x, q_w, k_ws, v_ws, g_w, o_w, b_ws, a_w, A_log, dtb,
                                   xhi, xlo, wch, wcl, owh, owl, be0, be1, gd);

    // 2) merged projection GEMM
    hgemm2<<<dim3(PROJ_W/128, RROWS/128), 256, HSM3>>>(xhi, xlo, wch, wcl, proj, RROWS, PROJ_W, HID);

    // 3) all convs (single launch)
    conv_all<<<CONV_QK_BLOCKS + CONV_V_BLOCKS, 256>>>(proj, qcw, kcw, vcw, qn, kn0, kn1, vs0, vs1);

    // 4) sequential gated delta rule   (launch #4 -> ncu capture target)
    delta_recur2<<<dim3(BSZ * HH, DV / 16), 128>>>(qn, kn0, kn1, vs0, vs1, be0, be1, gd, ob);

    // 5) output norm + gate (emits bf16 hi/lo)
    rms_gate<<<dim3(RROWS, HH), 256>>>(ob, proj, onw, ybh, ybl);

    // 6) final projection
    hgemm2<<<dim3(HID/128, RROWS/128), 256, HSM3>>>(ybh, ybl, owh, owl, out, RROWS, HID, VAL_DIM);
}

// round 14
// speedup vs baseline: 1.5343x; 1.5343x over previous
#include <cuda_runtime.h>
#include <cuda_bf16.h>
#include <cstdint>

// ---------------- problem constants ----------------
#define BSZ 2
#define TLEN 1024
#define HID 2048
#define NHEADS 2
#define HH 6
#define DK 256
#define DV 512
#define KEY_DIM 1536   // HH*DK
#define VAL_DIM 3072   // HH*DV
#define RROWS 2048     // BSZ*TLEN

// concatenated projection layout: [ q | k0 | k1 | v0 | v1 | gate ]
#define PROJ_W 13824
#define OFF_Q  0
#define OFF_K0 1536
#define OFF_K1 3072
#define OFF_V0 4608
#define OFF_V1 7680
#define OFF_G  10752

// ---------------- scratch (static device memory; no allocs) ----------------
__device__ float g_proj[(size_t)RROWS * PROJ_W];
__device__ __nv_bfloat16 g_xhi[(size_t)RROWS * HID];
__device__ __nv_bfloat16 g_xlo[(size_t)RROWS * HID];
__device__ __nv_bfloat16 g_wch[(size_t)HID * PROJ_W];
__device__ __nv_bfloat16 g_wcl[(size_t)HID * PROJ_W];
__device__ __nv_bfloat16 g_owh[(size_t)VAL_DIM * HID];
__device__ __nv_bfloat16 g_owl[(size_t)VAL_DIM * HID];
__device__ __nv_bfloat16 g_ybh[(size_t)RROWS * VAL_DIM];
__device__ __nv_bfloat16 g_ybl[(size_t)RROWS * VAL_DIM];
__device__ float g_qn [RROWS*KEY_DIM];
__device__ float g_kn0[RROWS*KEY_DIM];
__device__ float g_kn1[RROWS*KEY_DIM];
__device__ float g_vs0[RROWS*VAL_DIM];
__device__ float g_vs1[RROWS*VAL_DIM];
__device__ float g_ob [RROWS*VAL_DIM];
__device__ float g_be0[RROWS*HH];
__device__ float g_be1[RROWS*HH];
__device__ float g_gd [RROWS*HH];

// ================= helpers =================
__device__ __forceinline__ uint32_t smem_u32(const void* p) {
    uint32_t a;
    asm("{ .reg .u64 t; cvta.to.shared.u64 t, %1; cvt.u32.u64 %0, t; }" : "=r"(a) : "l"(p));
    return a;
}
__device__ __forceinline__ void ldmx4(uint32_t* r, uint32_t addr) {
    asm volatile("ldmatrix.sync.aligned.m8n8.x4.shared.b16 {%0,%1,%2,%3}, [%4];"
        : "=r"(r[0]), "=r"(r[1]), "=r"(r[2]), "=r"(r[3]) : "r"(addr));
}
__device__ __forceinline__ void ldmx2t(uint32_t* r, uint32_t addr) {
    asm volatile("ldmatrix.sync.aligned.m8n8.x2.trans.shared.b16 {%0,%1}, [%2];"
        : "=r"(r[0]), "=r"(r[1]) : "r"(addr));
}
__device__ __forceinline__ void mma16816(float* c, const uint32_t* a, const uint32_t* b) {
    asm volatile(
        "mma.sync.aligned.m16n8k16.row.col.f32.bf16.bf16.f32 "
        "{%0,%1,%2,%3}, {%4,%5,%6,%7}, {%8,%9}, {%0,%1,%2,%3};"
        : "+f"(c[0]), "+f"(c[1]), "+f"(c[2]), "+f"(c[3])
        : "r"(a[0]), "r"(a[1]), "r"(a[2]), "r"(a[3]), "r"(b[0]), "r"(b[1]));
}
__device__ __forceinline__ void cpa16(uint32_t dst, const void* src) {
    asm volatile("cp.async.cg.shared.global [%0], [%1], 16;" :: "r"(dst), "l"(src));
}

__device__ __forceinline__ void split_write(
    float4 v, __nv_bfloat16* __restrict__ h, __nv_bfloat16* __restrict__ l, size_t d)
{
    __nv_bfloat162 h0 = __floats2bfloat162_rn(v.x, v.y);
    __nv_bfloat162 h1 = __floats2bfloat162_rn(v.z, v.w);
    __nv_bfloat162 l0 = __floats2bfloat162_rn(v.x - __low2float(h0), v.y - __high2float(h0));
    __nv_bfloat162 l1 = __floats2bfloat162_rn(v.z - __low2float(h1), v.w - __high2float(h1));
    *reinterpret_cast<__nv_bfloat162*>(h + d)     = h0;
    *reinterpret_cast<__nv_bfloat162*>(h + d + 2) = h1;
    *reinterpret_cast<__nv_bfloat162*>(l + d)     = l0;
    *reinterpret_cast<__nv_bfloat162*>(l + d + 2) = l1;
}

// ================= fp32 -> bf16 hi/lo split (plain) =================
__global__ void cvt_split(const float* __restrict__ s,
                          __nv_bfloat16* __restrict__ h, __nv_bfloat16* __restrict__ l, int n)
{
    int i = (blockIdx.x * blockDim.x + threadIdx.x) * 4;
    if (i >= n) return;
    split_write(*reinterpret_cast<const float4*>(s + i), h, l, i);
}

// ================= ALL weight conversions in ONE launch =================
#define CVTW_BLOCKS 33792
__global__ void cvt_w_all(
    const float* __restrict__ q_w, const float* __restrict__ k_ws,
    const float* __restrict__ v_ws, const float* __restrict__ g_w,
    const float* __restrict__ o_w,
    __nv_bfloat16* __restrict__ wch, __nv_bfloat16* __restrict__ wcl,
    __nv_bfloat16* __restrict__ owh, __nv_bfloat16* __restrict__ owl)
{
    int qd = blockIdx.x * blockDim.x + threadIdx.x;   // quad index
    const float* s;
    int Ns, off;
    if (qd < 2359296) {
        int seg = qd / 786432;
        qd -= seg * 786432;
        s = (seg == 0) ? q_w : k_ws + (size_t)(seg - 1) * ((size_t)HID * KEY_DIM);
        Ns = KEY_DIM; off = seg * KEY_DIM;
    } else if (qd < 7077888) {
        int qq = qd - 2359296;
        int seg = qq / 1572864;
        qd = qq - seg * 1572864;
        s = (seg == 2) ? g_w : v_ws + (size_t)seg * ((size_t)HID * VAL_DIM);
        Ns = VAL_DIM; off = OFF_V0 + seg * VAL_DIM;
    } else {
        int i = (qd - 7077888) * 4;
        split_write(*reinterpret_cast<const float4*>(o_w + i), owh, owl, (size_t)i);
        return;
    }
    int i = qd * 4;
    int k = i / Ns, n = i - k * Ns;
    size_t d = (size_t)k * PROJ_W + off + n;
    split_write(*reinterpret_cast<const float4*>(s + i), wch, wcl, d);
}

// ---------------- fused tiny projections (b0|b1|a) + activations ----------------
__global__ __launch_bounds__(128) void gemm18b(
    const float* __restrict__ A, const float* __restrict__ b_ws,
    const float* __restrict__ a_w, const float* __restrict__ A_log,
    const float* __restrict__ dtb,
    float* __restrict__ be0, float* __restrict__ be1, float* __restrict__ gd)
{
    __shared__ float red[128 * 40];
    const int r0 = blockIdx.x * 2, tid = threadIdx.x;
    const int k0 = tid * 16;
    float acc[2][18];
#pragma unroll
    for (int rr = 0; rr < 2; rr++)
#pragma unroll
        for (int j = 0; j < 18; j++) acc[rr][j] = 0.f;

    const float* a0 = A + (size_t)r0 * HID + k0;
    const float* a1 = a0 + HID;
    float xa[2][16];
#pragma unroll
    for (int q = 0; q < 4; q++) {
        float4 v0 = *reinterpret_cast<const float4*>(a0 + q * 4);
        float4 v1 = *reinterpret_cast<const float4*>(a1 + q * 4);
        xa[0][q*4+0]=v0.x; xa[0][q*4+1]=v0.y; xa[0][q*4+2]=v0.z; xa[0][q*4+3]=v0.w;
        xa[1][q*4+0]=v1.x; xa[1][q*4+1]=v1.y; xa[1][q*4+2]=v1.z; xa[1][q*4+3]=v1.w;
    }

    const float* wp[3];
    wp[0] = b_ws + (size_t)k0 * 6;
    wp[1] = b_ws + (size_t)HID * 6 + (size_t)k0 * 6;
    wp[2] = a_w + (size_t)k0 * 6;
#pragma unroll
    for (int m = 0; m < 3; m++) {
        const float* w = wp[m];
#pragma unroll
        for (int kk = 0; kk < 16; kk += 2) {
            float4 w0 = *reinterpret_cast<const float4*>(w + kk * 6);
            float4 w1 = *reinterpret_cast<const float4*>(w + kk * 6 + 4);
            float4 w2 = *reinterpret_cast<const float4*>(w + kk * 6 + 8);
            float wv[12] = {w0.x,w0.y,w0.z,w0.w, w1.x,w1.y,w1.z,w1.w, w2.x,w2.y,w2.z,w2.w};
#pragma unroll
            for (int rr = 0; rr < 2; rr++) {
                float aA = xa[rr][kk], aB = xa[rr][kk + 1];
#pragma unroll
                for (int j = 0; j < 6; j++) {
                    acc[rr][m*6+j] = fmaf(aA, wv[j],     acc[rr][m*6+j]);
                    acc[rr][m*6+j] = fmaf(aB, wv[6 + j], acc[rr][m*6+j]);
                }
            }
        }
    }
#pragma unroll
    for (int rr = 0; rr < 2; rr++)
#pragma unroll
        for (int j = 0; j < 18; j++) red[tid * 40 + rr * 20 + j] = acc[rr][j];
    __syncthreads();
    for (int s = 64; s > 0; s >>= 1) {
        if (tid < s) {
#pragma unroll
            for (int j = 0; j < 40; j++) red[tid * 40 + j] += red[(tid + s) * 40 + j];
        }
        __syncthreads();
    }
    if (tid < 36) {
        int rr = tid / 18, u = tid % 18;
        float v = red[rr * 20 + u];
        int r = r0 + rr;
        int j = u % 6;
        if (u < 6) {
            be0[r * 6 + j] = 1.f / (1.f + expf(-v));
        } else if (u < 12) {
            be1[r * 6 + j] = 1.f / (1.f + expf(-v));
        } else {
            float z = v + dtb[j];
            float sp = (z > 20.f) ? z : log1pf(expf(z));
            gd[r * 6 + j] = -expf(A_log[j]) * sp;
        }
    }
}

// ================= bf16x3 HMMA GEMM, 3-stage cp.async =================
#define HSTG 36864
#define HSM3 (3 * HSTG)

__device__ __forceinline__ void issue_stage(
    uint32_t st,
    const __nv_bfloat16* __restrict__ Ahi, const __nv_bfloat16* __restrict__ Alo,
    const __nv_bfloat16* __restrict__ Bhi, const __nv_bfloat16* __restrict__ Blo,
    int bm, int bn, int kt, int N, int K, int tid)
{
#pragma unroll
    for (int hq = 0; hq < 2; hq++) {
        int c = tid + hq * 256;
        int m = c >> 2, sl = c & 3;
        size_t so = (size_t)(bm + m) * K + kt + sl * 8;
        uint32_t d = st + m * 80 + sl * 16;
        cpa16(d,          Ahi + so);
        cpa16(d + 10240,  Alo + so);
    }
#pragma unroll
    for (int hq = 0; hq < 2; hq++) {
        int c = tid + hq * 256;
        int k = c >> 4, n8 = c & 15;
        size_t so = (size_t)(kt + k) * N + bn + n8 * 8;
        uint32_t sw = (uint32_t)(((n8 & 8) | ((n8 ^ k) & 7)) * 16);
        uint32_t d = st + 20480 + k * 256 + sw;
        cpa16(d,         Bhi + so);
        cpa16(d + 8192,  Blo + so);
    }
}

__global__ void __launch_bounds__(256, 2) hgemm2(
    const __nv_bfloat16* __restrict__ Ahi, const __nv_bfloat16* __restrict__ Alo,
    const __nv_bfloat16* __restrict__ Bhi, const __nv_bfloat16* __restrict__ Blo,
    float* __restrict__ C, int M, int N, int K)
{
    extern __shared__ char sm2[];
    const uint32_t sbase = smem_u32(sm2);
    const int tid = threadIdx.x, lane = tid & 31, w = tid >> 5;
    const int wm = (w >> 2) * 64, wn = (w & 3) * 32;
    const int bm = blockIdx.y * 128, bn = blockIdx.x * 128;
    const int wslot = (w & 3) * 4;

    float acc[4][4][4];
#pragma unroll
    for (int i = 0; i < 4; i++)
#pragma unroll
        for (int j = 0; j < 4; j++)
#pragma unroll
            for (int q = 0; q < 4; q++) acc[i][j][q] = 0.f;

    const int niter = K >> 5;
    const uint32_t a_lane = (uint32_t)((wm + (lane & 15)) * 80 + ((lane >> 4) << 4));

    issue_stage(sbase,        Ahi, Alo, Bhi, Blo, bm, bn, 0,  N, K, tid);
    asm volatile("cp.async.commit_group;" ::: "memory");
    issue_stage(sbase + HSTG, Ahi, Alo, Bhi, Blo, bm, bn, 32, N, K, tid);
    asm volatile("cp.async.commit_group;" ::: "memory");

    int cbuf = 0;
    int ibuf = 2;
    for (int it = 0; it < niter; ++it) {
        if (it + 2 < niter) {
            issue_stage(sbase + (uint32_t)ibuf * HSTG,
                        Ahi, Alo, Bhi, Blo, bm, bn, (it + 2) << 5, N, K, tid);
            asm volatile("cp.async.commit_group;" ::: "memory");
            asm volatile("cp.async.wait_group 2;" ::: "memory");
            if (++ibuf == 3) ibuf = 0;
        } else if (it + 1 < niter) {
            asm volatile("cp.async.wait_group 1;" ::: "memory");
        } else {
            asm volatile("cp.async.wait_group 0;" ::: "memory");
        }
        __syncthreads();

        const uint32_t sA   = sbase + (uint32_t)cbuf * HSTG;
        const uint32_t sAlo = sA + 10240;
        const uint32_t sB   = sA + 20480;
        const uint32_t sBlo = sB + 8192;

#pragma unroll
        for (int ks = 0; ks < 32; ks += 16) {
            const int klane = ks + (lane & 15);
            const uint32_t bro = (uint32_t)(klane * 256);
            uint32_t bh[4][2], bl[4][2];
#pragma unroll
            for (int ni = 0; ni < 4; ni++) {
                const int slot = wslot + ni;
                const uint32_t off = bro + (uint32_t)((((slot ^ klane) & 7) | (slot & 8)) * 16);
                ldmx2t(bh[ni], sB + off);
                ldmx2t(bl[ni], sBlo + off);
            }
            const uint32_t ao = a_lane + ks * 2;
#pragma unroll
            for (int mi = 0; mi < 4; mi++) {
                uint32_t ah[4], al_[4];
                ldmx4(ah,  sA   + ao + mi * (16 * 80));
                ldmx4(al_, sAlo + ao + mi * (16 * 80));
#pragma unroll
                for (int ni = 0; ni < 4; ni++) {
                    mma16816(acc[mi][ni], ah,  bh[ni]);
                    mma16816(acc[mi][ni], al_, bh[ni]);
                    mma16816(acc[mi][ni], ah,  bl[ni]);
                }
            }
        }
        __syncthreads();
        if (++cbuf == 3) cbuf = 0;
    }

    // epilogue
#pragma unroll
    for (int mi = 0; mi < 4; mi++) {
        const int row = bm + wm + mi * 16 + (lane >> 2);
#pragma unroll
        for (int ni = 0; ni < 4; ni++) {
            const int col = bn + wn + ni * 8 + (lane & 3) * 2;
            float2 v0; v0.x = acc[mi][ni][0]; v0.y = acc[mi][ni][1];
            float2 v1; v1.x = acc[mi][ni][2]; v1.y = acc[mi][ni][3];
            *reinterpret_cast<float2*>(C + (size_t)row * N + col)       = v0;
            *reinterpret_cast<float2*>(C + (size_t)(row + 8) * N + col) = v1;
        }
    }
}

// ================= ALL convolutions in ONE launch =================
#define CONV_QK_BLOCKS (RROWS * 18)
#define CONV_V_BLOCKS  ((RROWS * VAL_DIM * 2) / 256)
__global__ __launch_bounds__(256) void conv_all(
    const float* __restrict__ Z, const float* __restrict__ qcw,
    const float* __restrict__ kcw, const float* __restrict__ vcw,
    float* __restrict__ qn, float* __restrict__ kn0, float* __restrict__ kn1,
    float* __restrict__ vs0, float* __restrict__ vs1)
{
    const int bid = blockIdx.x, tid = threadIdx.x;
    if (bid < CONV_QK_BLOCKS) {
        const int r = bid / 18, u = bid - (bid / 18) * 18;
        const int tsel = u / 6, h = u - tsel * 6;
        const int zoff = tsel * KEY_DIM;
        const float* W = (tsel == 0) ? qcw : kcw + (size_t)(tsel - 1) * (KEY_DIM * 4);
        const float outscale = (tsel == 0) ? 0.0625f : 1.f;
        float* Out = (tsel == 0) ? qn : ((tsel == 1) ? kn0 : kn1);

        const int b = r >> 10, t = r & 1023;
        const int c = h * DK + tid;
        float acc = 0.f;
#pragma unroll
        for (int j = 0; j < 4; j++) {
            int tj = t - 3 + j;
            if (tj >= 0) acc = fmaf(Z[(size_t)(b * TLEN + tj) * PROJ_W + zoff + c], W[c * 4 + j], acc);
        }
        float y = acc / (1.f + expf(-acc));
        __shared__ float sred[256];
        sred[tid] = y * y;
        __syncthreads();
        for (int s = 128; s > 0; s >>= 1) {
            if (tid < s) sred[tid] += sred[tid + s];
            __syncthreads();
        }
        float scale = rsqrtf(sred[0] + 1e-12f) * outscale;
        Out[(size_t)r * KEY_DIM + c] = y * scale;
    } else {
        int idx = (bid - CONV_QK_BLOCKS) * 256 + tid;
        const int vsel = (idx >= RROWS * VAL_DIM) ? 1 : 0;
        idx -= vsel * (RROWS * VAL_DIM);
        const int zoff = OFF_V0 + vsel * VAL_DIM;
        const float* W = vcw + (size_t)vsel * (VAL_DIM * 4);
        float* Out = vsel ? vs1 : vs0;

        const int c = idx % VAL_DIM;
        const int r = idx / VAL_DIM;
        const int b = r >> 10, t = r & 1023;
        float acc = 0.f;
#pragma unroll
        for (int j = 0; j < 4; j++) {
            int tj = t - 3 + j;
            if (tj >= 0) acc = fmaf(Z[(size_t)(b * TLEN + tj) * PROJ_W + zoff + c], W[c * 4 + j], acc);
        }
        Out[idx] = acc / (1.f + expf(-acc));
    }
}

// ---------------- packed f32x2 helpers ----------------
union F2U { float2 f; unsigned long long u; };

__device__ __forceinline__ F2U ffma2(F2U a, F2U b, F2U c) {
    F2U r;
    asm("fma.rn.f32x2 %0, %1, %2, %3;" : "=l"(r.u) : "l"(a.u), "l"(b.u), "l"(c.u));
    return r;
}
__device__ __forceinline__ F2U fmul2(F2U a, F2U b) {
    F2U r;
    asm("mul.rn.f32x2 %0, %1, %2;" : "=l"(r.u) : "l"(a.u), "l"(b.u));
    return r;
}

// ---------------- gated delta-rule recurrence v3: single fused dot/reduce phase ----------------
// Telescoped macro step (all dots against the SAME pre-step S):
//   u0 = (v0 - decay*(k0.S))*b0
//   u1 = (v1 - decay*(k1.S) - (k0.k1)*u0)*b1
//   o  = decay*(q.S) + (q.k0)*u0 + (q.k1)*u1
//   S  = decay*S + k0 u0^T + k1 u1^T
// One fused sweep computes 6 column dots + 3 scalar dots (9 independent FFMA2 chains),
// ONE 4-deep shfl phase reduces all 9, then one fused update sweep (k0/k1 still in regs).
// 128 threads = 4 warps; half-warp owns 2 columns; triple-buffered staging + prefetch.
__global__ void __launch_bounds__(128, 3) delta_recur3(
    const float* __restrict__ Qn,  const float* __restrict__ Kn0, const float* __restrict__ Kn1,
    const float* __restrict__ Vs0, const float* __restrict__ Vs1,
    const float* __restrict__ Be0, const float* __restrict__ Be1,
    const float* __restrict__ Gd,  float* __restrict__ O)
{
    const int bh = blockIdx.x;
    const int b = bh / HH, h = bh % HH;
    const int tid = threadIdx.x;
    const int w = tid >> 5, lane = tid & 31;
    const int half = lane >> 4, l0 = lane & 15;
    const int col0 = blockIdx.y * 16 + w * 4 + half * 2;

    __shared__ __align__(16) float sk[3][3][256];   // [buf][k0,k1,q][dim]

    F2U S0[8], S1[8];
#pragma unroll
    for (int j = 0; j < 8; j++) { S0[j].u = 0ull; S1[j].u = 0ull; }

    {
        const size_t kb = (size_t)(b * TLEN) * KEY_DIM + h * DK + tid * 2;
        *reinterpret_cast<float2*>(&sk[0][0][tid * 2]) = *reinterpret_cast<const float2*>(Kn0 + kb);
        *reinterpret_cast<float2*>(&sk[0][1][tid * 2]) = *reinterpret_cast<const float2*>(Kn1 + kb);
        *reinterpret_cast<float2*>(&sk[0][2][tid * 2]) = *reinterpret_cast<const float2*>(Qn + kb);
    }
    const size_t vb0 = (size_t)(b * TLEN) * VAL_DIM + h * DV + col0;
    float2 vc0 = *reinterpret_cast<const float2*>(Vs0 + vb0);
    float2 vc1 = *reinterpret_cast<const float2*>(Vs1 + vb0);
    const int gi0 = (b * TLEN) * HH + h;
    float gcur = Gd[gi0], b0cur = Be0[gi0], b1cur = Be1[gi0];
    __syncthreads();

    int cur = 0;
    for (int t = 0; t < TLEN; t++) {
        const int nxt = (cur == 2) ? 0 : cur + 1;
        const int r = b * TLEN + t;
        const bool more = (t + 1 < TLEN);

        // prefetch t+1
        float2 kr0, kr1, krq, vn0, vn1;
        float gn = 0.f, bn0 = 0.f, bn1 = 0.f;
        if (more) {
            const size_t kb = (size_t)(r + 1) * KEY_DIM + h * DK + tid * 2;
            kr0 = *reinterpret_cast<const float2*>(Kn0 + kb);
            kr1 = *reinterpret_cast<const float2*>(Kn1 + kb);
            krq = *reinterpret_cast<const float2*>(Qn + kb);
            const size_t vb = (size_t)(r + 1) * VAL_DIM + h * DV + col0;
            vn0 = *reinterpret_cast<const float2*>(Vs0 + vb);
            vn1 = *reinterpret_cast<const float2*>(Vs1 + vb);
            const int gi = (r + 1) * HH + h;
            gn = Gd[gi]; bn0 = Be0[gi]; bn1 = Be1[gi];
        }

        const float decay = expf(gcur);
        const float2* pk0 = reinterpret_cast<const float2*>(sk[cur][0]);
        const float2* pk1 = reinterpret_cast<const float2*>(sk[cur][1]);
        const float2* pq  = reinterpret_cast<const float2*>(sk[cur][2]);

        // ---- load k0, k1, q slices ----
        F2U rk0[8], rk1[8], rq[8];
#pragma unroll
        for (int j = 0; j < 8; j++) {
            rk0[j].f = pk0[j * 16 + l0];
            rk1[j].f = pk1[j * 16 + l0];
            rq [j].f = pq [j * 16 + l0];
        }

        // ---- fused dots: 6 column dots + 3 scalar dots (9 independent chains) ----
        F2U a00, a01, a10, a11, aq0, aq1, c01, cq0, cq1;
        a00.u=0; a01.u=0; a10.u=0; a11.u=0; aq0.u=0; aq1.u=0; c01.u=0; cq0.u=0; cq1.u=0;
#pragma unroll
        for (int j = 0; j < 8; j++) {
            a00 = ffma2(rk0[j], S0[j], a00);
            a01 = ffma2(rk0[j], S1[j], a01);
            a10 = ffma2(rk1[j], S0[j], a10);
            a11 = ffma2(rk1[j], S1[j], a11);
            aq0 = ffma2(rq[j],  S0[j], aq0);
            aq1 = ffma2(rq[j],  S1[j], aq1);
            c01 = ffma2(rk0[j], rk1[j], c01);
            cq0 = ffma2(rq[j],  rk0[j], cq0);
            cq1 = ffma2(rq[j],  rk1[j], cq1);
        }
        float d00 = a00.f.x + a00.f.y, d01 = a01.f.x + a01.f.y;
        float d10 = a10.f.x + a10.f.y, d11 = a11.f.x + a11.f.y;
        float dq0 = aq0.f.x + aq0.f.y, dq1 = aq1.f.x + aq1.f.y;
        float s01 = c01.f.x + c01.f.y, sq0 = cq0.f.x + cq0.f.y, sq1 = cq1.f.x + cq1.f.y;

        // ---- ONE shfl reduction phase (9 values, depth 4, independent) ----
#pragma unroll
        for (int m = 8; m > 0; m >>= 1) {
            d00 += __shfl_xor_sync(0xffffffffu, d00, m);
            d01 += __shfl_xor_sync(0xffffffffu, d01, m);
            d10 += __shfl_xor_sync(0xffffffffu, d10, m);
            d11 += __shfl_xor_sync(0xffffffffu, d11, m);
            dq0 += __shfl_xor_sync(0xffffffffu, dq0, m);
            dq1 += __shfl_xor_sync(0xffffffffu, dq1, m);
            s01 += __shfl_xor_sync(0xffffffffu, s01, m);
            sq0 += __shfl_xor_sync(0xffffffffu, sq0, m);
            sq1 += __shfl_xor_sync(0xffffffffu, sq1, m);
        }

        // ---- scalar math ----
        const float u0A = (vc0.x - decay * d00) * b0cur;
        const float u0B = (vc0.y - decay * d01) * b0cur;
        const float u1A = (vc1.x - decay * d10 - s01 * u0A) * b1cur;
        const float u1B = (vc1.y - decay * d11 - s01 * u0B) * b1cur;
        if (l0 == 0) {
            float2 ov;
            ov.x = decay * dq0 + sq0 * u0A + sq1 * u1A;
            ov.y = decay * dq1 + sq0 * u0B + sq1 * u1B;
            *reinterpret_cast<float2*>(O + (size_t)(r * HH + h) * DV + col0) = ov;
        }

        // ---- fused update: S = decay*S + k0 u0 + k1 u1 (k0/k1 still in regs) ----
        F2U dec2; dec2.f = make_float2(decay, decay);
        F2U u0Av; u0Av.f = make_float2(u0A, u0A);
        F2U u0Bv; u0Bv.f = make_float2(u0B, u0B);
        F2U u1Av; u1Av.f = make_float2(u1A, u1A);
        F2U u1Bv; u1Bv.f = make_float2(u1B, u1B);
#pragma unroll
        for (int j = 0; j < 8; j++) {
            S0[j] = ffma2(S0[j], dec2, ffma2(rk0[j], u0Av, fmul2(rk1[j], u1Av)));
            S1[j] = ffma2(S1[j], dec2, ffma2(rk0[j], u0Bv, fmul2(rk1[j], u1Bv)));
        }

        // ---- stage t+1 ----
        if (more) {
            *reinterpret_cast<float2*>(&sk[nxt][0][tid * 2]) = kr0;
            *reinterpret_cast<float2*>(&sk[nxt][1][tid * 2]) = kr1;
            *reinterpret_cast<float2*>(&sk[nxt][2][tid * 2]) = krq;
            vc0 = vn0; vc1 = vn1; gcur = gn; b0cur = bn0; b1cur = bn1;
            __syncthreads();
        }
        cur = nxt;
    }
}

// ---------------- RMS norm over DV + gated SiLU -> bf16 hi/lo ----------------
__global__ __launch_bounds__(256) void rms_gate(
    const float* __restrict__ Ob, const float* __restrict__ Gx,
    const float* __restrict__ onw,
    __nv_bfloat16* __restrict__ Yh, __nv_bfloat16* __restrict__ Yl)
{
    const int r = blockIdx.x, h = blockIdx.y, tid = threadIdx.x;
    const size_t base = (size_t)(r * HH + h) * DV;
    const size_t gbase = (size_t)r * PROJ_W + OFF_G + h * DV;
    float o0 = Ob[base + tid], o1 = Ob[base + tid + 256];
    __shared__ float sred[256];
    sred[tid] = o0 * o0 + o1 * o1;
    __syncthreads();
    for (int s = 128; s > 0; s >>= 1) {
        if (tid < s) sred[tid] += sred[tid + s];
        __syncthreads();
    }
    float scale = rsqrtf(sred[0] * (1.f / 512.f) + 1e-5f);
    float g0 = Gx[gbase + tid], g1 = Gx[gbase + tid + 256];
    float y0 = o0 * scale * onw[tid]       * (g0 / (1.f + expf(-g0)));
    float y1 = o1 * scale * onw[tid + 256] * (g1 / (1.f + expf(-g1)));
    __nv_bfloat16 h0 = __float2bfloat16_rn(y0);
    __nv_bfloat16 h1 = __float2bfloat16_rn(y1);
    Yh[base + tid]       = h0;
    Yh[base + tid + 256] = h1;
    Yl[base + tid]       = __float2bfloat16_rn(y0 - __bfloat162float(h0));
    Yl[base + tid + 256] = __float2bfloat16_rn(y1 - __bfloat162float(h1));
}

// ---------------- launch ----------------
extern "C" void kernel_launch(void* const* d_in, const int* in_sizes, int n_in,
                              void* d_out, int out_size)
{
    const float* x     = (const float*)d_in[0];
    const float* q_w   = (const float*)d_in[1];
    const float* k_ws  = (const float*)d_in[2];
    const float* v_ws  = (const float*)d_in[3];
    const float* b_ws  = (const float*)d_in[4];
    const float* a_w   = (const float*)d_in[5];
    const float* g_w   = (const float*)d_in[6];
    const float* o_w   = (const float*)d_in[7];
    const float* qcw   = (const float*)d_in[8];
    const float* kcw   = (const float*)d_in[9];
    const float* vcw   = (const float*)d_in[10];
    const float* A_log = (const float*)d_in[11];
    const float* dtb   = (const float*)d_in[12];
    const float* onw   = (const float*)d_in[13];
    float* out = (float*)d_out;

    float *proj, *qn, *kn0, *kn1, *vs0, *vs1, *ob;
    float *be0, *be1, *gd;
    __nv_bfloat16 *xhi, *xlo, *wch, *wcl, *owh, *owl, *ybh, *ybl;
    cudaGetSymbolAddress((void**)&proj, g_proj);
    cudaGetSymbolAddress((void**)&xhi, g_xhi);
    cudaGetSymbolAddress((void**)&xlo, g_xlo);
    cudaGetSymbolAddress((void**)&wch, g_wch);
    cudaGetSymbolAddress((void**)&wcl, g_wcl);
    cudaGetSymbolAddress((void**)&owh, g_owh);
    cudaGetSymbolAddress((void**)&owl, g_owl);
    cudaGetSymbolAddress((void**)&ybh, g_ybh);
    cudaGetSymbolAddress((void**)&ybl, g_ybl);
    cudaGetSymbolAddress((void**)&qn,  g_qn);
    cudaGetSymbolAddress((void**)&kn0, g_kn0);
    cudaGetSymbolAddress((void**)&kn1, g_kn1);
    cudaGetSymbolAddress((void**)&vs0, g_vs0);
    cudaGetSymbolAddress((void**)&vs1, g_vs1);
    cudaGetSymbolAddress((void**)&ob,  g_ob);
    cudaGetSymbolAddress((void**)&be0, g_be0);
    cudaGetSymbolAddress((void**)&be1, g_be1);
    cudaGetSymbolAddress((void**)&gd,  g_gd);

    cudaFuncSetAttribute(hgemm2, cudaFuncAttributeMaxDynamicSharedMemorySize, HSM3);

    // 1) input split
    {
        int n = RROWS * HID;
        cvt_split<<<(n/4 + 255)/256, 256>>>(x, xhi, xlo, n);
    }
    // 2) all weight splits (single launch)
    cvt_w_all<<<CVTW_BLOCKS, 256>>>(q_w, k_ws, v_ws, g_w, o_w, wch, wcl, owh, owl);

    // 3) fused tiny projections + activations
    gemm18b<<<RROWS / 2, 128>>>(x, b_ws, a_w, A_log, dtb, be0, be1, gd);

    // 4) merged projection GEMM   (launch #4 -> ncu capture target)
    hgemm2<<<dim3(PROJ_W/128, RROWS/128), 256, HSM3>>>(xhi, xlo, wch, wcl, proj, RROWS, PROJ_W, HID);

    // 5) all convs (single launch)
    conv_all<<<CONV_QK_BLOCKS + CONV_V_BLOCKS, 256>>>(proj, qcw, kcw, vcw, qn, kn0, kn1, vs0, vs1);

    // 6) sequential gated delta rule (fused-dot formulation)
    delta_recur3<<<dim3(BSZ * HH, DV / 16), 128>>>(qn, kn0, kn1, vs0, vs1, be0, be1, gd, ob);

    // 7) output norm + gate (emits bf16 hi/lo)
    rms_gate<<<dim3(RROWS, HH), 256>>>(ob, proj, onw, ybh, ybl);

    // 8) final projection
    hgemm2<<<dim3(HID/128, RROWS/128), 256, HSM3>>>(ybh, ybl, owh, owl, out, RROWS, HID, VAL_DIM);
}

// round 15
// speedup vs baseline: 1.5898x; 1.0361x over previous
#include <cuda_runtime.h>
#include <cuda_bf16.h>
#include <cstdint>

// ---------------- problem constants ----------------
#define BSZ 2
#define TLEN 1024
#define HID 2048
#define NHEADS 2
#define HH 6
#define DK 256
#define DV 512
#define KEY_DIM 1536   // HH*DK
#define VAL_DIM 3072   // HH*DV
#define RROWS 2048     // BSZ*TLEN

// concatenated projection layout: [ q | k0 | k1 | v0 | v1 | gate ]
#define PROJ_W 13824
#define OFF_Q  0
#define OFF_K0 1536
#define OFF_K1 3072
#define OFF_V0 4608
#define OFF_V1 7680
#define OFF_G  10752

// ---------------- scratch (static device memory; no allocs) ----------------
__device__ float g_proj[(size_t)RROWS * PROJ_W];
__device__ __nv_bfloat16 g_xhi[(size_t)RROWS * HID];
__device__ __nv_bfloat16 g_xlo[(size_t)RROWS * HID];
__device__ __nv_bfloat16 g_wch[(size_t)HID * PROJ_W];
__device__ __nv_bfloat16 g_wcl[(size_t)HID * PROJ_W];
__device__ __nv_bfloat16 g_owh[(size_t)VAL_DIM * HID];
__device__ __nv_bfloat16 g_owl[(size_t)VAL_DIM * HID];
__device__ __nv_bfloat16 g_ybh[(size_t)RROWS * VAL_DIM];
__device__ __nv_bfloat16 g_ybl[(size_t)RROWS * VAL_DIM];
__device__ float g_qn [RROWS*KEY_DIM];
__device__ float g_kn0[RROWS*KEY_DIM];
__device__ float g_kn1[RROWS*KEY_DIM];
__device__ float g_vs0[RROWS*VAL_DIM];
__device__ float g_vs1[RROWS*VAL_DIM];
__device__ float g_ob [RROWS*VAL_DIM];
__device__ float g_be0[RROWS*HH];
__device__ float g_be1[RROWS*HH];
__device__ float g_gd [RROWS*HH];

// ================= helpers =================
__device__ __forceinline__ uint32_t smem_u32(const void* p) {
    uint32_t a;
    asm("{ .reg .u64 t; cvta.to.shared.u64 t, %1; cvt.u32.u64 %0, t; }" : "=r"(a) : "l"(p));
    return a;
}
__device__ __forceinline__ void ldmx4(uint32_t* r, uint32_t addr) {
    asm volatile("ldmatrix.sync.aligned.m8n8.x4.shared.b16 {%0,%1,%2,%3}, [%4];"
        : "=r"(r[0]), "=r"(r[1]), "=r"(r[2]), "=r"(r[3]) : "r"(addr));
}
__device__ __forceinline__ void ldmx2t(uint32_t* r, uint32_t addr) {
    asm volatile("ldmatrix.sync.aligned.m8n8.x2.trans.shared.b16 {%0,%1}, [%2];"
        : "=r"(r[0]), "=r"(r[1]) : "r"(addr));
}
__device__ __forceinline__ void mma16816(float* c, const uint32_t* a, const uint32_t* b) {
    asm volatile(
        "mma.sync.aligned.m16n8k16.row.col.f32.bf16.bf16.f32 "
        "{%0,%1,%2,%3}, {%4,%5,%6,%7}, {%8,%9}, {%0,%1,%2,%3};"
        : "+f"(c[0]), "+f"(c[1]), "+f"(c[2]), "+f"(c[3])
        : "r"(a[0]), "r"(a[1]), "r"(a[2]), "r"(a[3]), "r"(b[0]), "r"(b[1]));
}
__device__ __forceinline__ void cpa16(uint32_t dst, const void* src) {
    asm volatile("cp.async.cg.shared.global [%0], [%1], 16;" :: "r"(dst), "l"(src));
}

__device__ __forceinline__ void split_write(
    float4 v, __nv_bfloat16* __restrict__ h, __nv_bfloat16* __restrict__ l, size_t d)
{
    __nv_bfloat162 h0 = __floats2bfloat162_rn(v.x, v.y);
    __nv_bfloat162 h1 = __floats2bfloat162_rn(v.z, v.w);
    __nv_bfloat162 l0 = __floats2bfloat162_rn(v.x - __low2float(h0), v.y - __high2float(h0));
    __nv_bfloat162 l1 = __floats2bfloat162_rn(v.z - __low2float(h1), v.w - __high2float(h1));
    *reinterpret_cast<__nv_bfloat162*>(h + d)     = h0;
    *reinterpret_cast<__nv_bfloat162*>(h + d + 2) = h1;
    *reinterpret_cast<__nv_bfloat162*>(l + d)     = l0;
    *reinterpret_cast<__nv_bfloat162*>(l + d + 2) = l1;
}

// ================= fp32 -> bf16 hi/lo split (plain) =================
__global__ void cvt_split(const float* __restrict__ s,
                          __nv_bfloat16* __restrict__ h, __nv_bfloat16* __restrict__ l, int n)
{
    int i = (blockIdx.x * blockDim.x + threadIdx.x) * 4;
    if (i >= n) return;
    split_write(*reinterpret_cast<const float4*>(s + i), h, l, i);
}

// ================= ALL weight conversions in ONE launch =================
#define CVTW_BLOCKS 33792
__global__ void cvt_w_all(
    const float* __restrict__ q_w, const float* __restrict__ k_ws,
    const float* __restrict__ v_ws, const float* __restrict__ g_w,
    const float* __restrict__ o_w,
    __nv_bfloat16* __restrict__ wch, __nv_bfloat16* __restrict__ wcl,
    __nv_bfloat16* __restrict__ owh, __nv_bfloat16* __restrict__ owl)
{
    int qd = blockIdx.x * blockDim.x + threadIdx.x;   // quad index
    const float* s;
    int Ns, off;
    if (qd < 2359296) {
        int seg = qd / 786432;
        qd -= seg * 786432;
        s = (seg == 0) ? q_w : k_ws + (size_t)(seg - 1) * ((size_t)HID * KEY_DIM);
        Ns = KEY_DIM; off = seg * KEY_DIM;
    } else if (qd < 7077888) {
        int qq = qd - 2359296;
        int seg = qq / 1572864;
        qd = qq - seg * 1572864;
        s = (seg == 2) ? g_w : v_ws + (size_t)seg * ((size_t)HID * VAL_DIM);
        Ns = VAL_DIM; off = OFF_V0 + seg * VAL_DIM;
    } else {
        int i = (qd - 7077888) * 4;
        split_write(*reinterpret_cast<const float4*>(o_w + i), owh, owl, (size_t)i);
        return;
    }
    int i = qd * 4;
    int k = i / Ns, n = i - k * Ns;
    size_t d = (size_t)k * PROJ_W + off + n;
    split_write(*reinterpret_cast<const float4*>(s + i), wch, wcl, d);
}

// ---------------- fused tiny projections (b0|b1|a) + activations ----------------
__global__ __launch_bounds__(128) void gemm18b(
    const float* __restrict__ A, const float* __restrict__ b_ws,
    const float* __restrict__ a_w, const float* __restrict__ A_log,
    const float* __restrict__ dtb,
    float* __restrict__ be0, float* __restrict__ be1, float* __restrict__ gd)
{
    __shared__ float red[128 * 40];
    const int r0 = blockIdx.x * 2, tid = threadIdx.x;
    const int k0 = tid * 16;
    float acc[2][18];
#pragma unroll
    for (int rr = 0; rr < 2; rr++)
#pragma unroll
        for (int j = 0; j < 18; j++) acc[rr][j] = 0.f;

    const float* a0 = A + (size_t)r0 * HID + k0;
    const float* a1 = a0 + HID;
    float xa[2][16];
#pragma unroll
    for (int q = 0; q < 4; q++) {
        float4 v0 = *reinterpret_cast<const float4*>(a0 + q * 4);
        float4 v1 = *reinterpret_cast<const float4*>(a1 + q * 4);
        xa[0][q*4+0]=v0.x; xa[0][q*4+1]=v0.y; xa[0][q*4+2]=v0.z; xa[0][q*4+3]=v0.w;
        xa[1][q*4+0]=v1.x; xa[1][q*4+1]=v1.y; xa[1][q*4+2]=v1.z; xa[1][q*4+3]=v1.w;
    }

    const float* wp[3];
    wp[0] = b_ws + (size_t)k0 * 6;
    wp[1] = b_ws + (size_t)HID * 6 + (size_t)k0 * 6;
    wp[2] = a_w + (size_t)k0 * 6;
#pragma unroll
    for (int m = 0; m < 3; m++) {
        const float* w = wp[m];
#pragma unroll
        for (int kk = 0; kk < 16; kk += 2) {
            float4 w0 = *reinterpret_cast<const float4*>(w + kk * 6);
            float4 w1 = *reinterpret_cast<const float4*>(w + kk * 6 + 4);
            float4 w2 = *reinterpret_cast<const float4*>(w + kk * 6 + 8);
            float wv[12] = {w0.x,w0.y,w0.z,w0.w, w1.x,w1.y,w1.z,w1.w, w2.x,w2.y,w2.z,w2.w};
#pragma unroll
            for (int rr = 0; rr < 2; rr++) {
                float aA = xa[rr][kk], aB = xa[rr][kk + 1];
#pragma unroll
                for (int j = 0; j < 6; j++) {
                    acc[rr][m*6+j] = fmaf(aA, wv[j],     acc[rr][m*6+j]);
                    acc[rr][m*6+j] = fmaf(aB, wv[6 + j], acc[rr][m*6+j]);
                }
            }
        }
    }
#pragma unroll
    for (int rr = 0; rr < 2; rr++)
#pragma unroll
        for (int j = 0; j < 18; j++) red[tid * 40 + rr * 20 + j] = acc[rr][j];
    __syncthreads();
    for (int s = 64; s > 0; s >>= 1) {
        if (tid < s) {
#pragma unroll
            for (int j = 0; j < 40; j++) red[tid * 40 + j] += red[(tid + s) * 40 + j];
        }
        __syncthreads();
    }
    if (tid < 36) {
        int rr = tid / 18, u = tid % 18;
        float v = red[rr * 20 + u];
        int r = r0 + rr;
        int j = u % 6;
        if (u < 6) {
            be0[r * 6 + j] = 1.f / (1.f + expf(-v));
        } else if (u < 12) {
            be1[r * 6 + j] = 1.f / (1.f + expf(-v));
        } else {
            float z = v + dtb[j];
            float sp = (z > 20.f) ? z : log1pf(expf(z));
            gd[r * 6 + j] = -expf(A_log[j]) * sp;
        }
    }
}

// ================= bf16x3 HMMA GEMM, 3-stage cp.async =================
#define HSTG 36864
#define HSM3 (3 * HSTG)

__device__ __forceinline__ void issue_stage(
    uint32_t st,
    const __nv_bfloat16* __restrict__ Ahi, const __nv_bfloat16* __restrict__ Alo,
    const __nv_bfloat16* __restrict__ Bhi, const __nv_bfloat16* __restrict__ Blo,
    int bm, int bn, int kt, int N, int K, int tid)
{
#pragma unroll
    for (int hq = 0; hq < 2; hq++) {
        int c = tid + hq * 256;
        int m = c >> 2, sl = c & 3;
        size_t so = (size_t)(bm + m) * K + kt + sl * 8;
        uint32_t d = st + m * 80 + sl * 16;
        cpa16(d,          Ahi + so);
        cpa16(d + 10240,  Alo + so);
    }
#pragma unroll
    for (int hq = 0; hq < 2; hq++) {
        int c = tid + hq * 256;
        int k = c >> 4, n8 = c & 15;
        size_t so = (size_t)(kt + k) * N + bn + n8 * 8;
        uint32_t sw = (uint32_t)(((n8 & 8) | ((n8 ^ k) & 7)) * 16);
        uint32_t d = st + 20480 + k * 256 + sw;
        cpa16(d,         Bhi + so);
        cpa16(d + 8192,  Blo + so);
    }
}

__global__ void __launch_bounds__(256, 2) hgemm2(
    const __nv_bfloat16* __restrict__ Ahi, const __nv_bfloat16* __restrict__ Alo,
    const __nv_bfloat16* __restrict__ Bhi, const __nv_bfloat16* __restrict__ Blo,
    float* __restrict__ C, int M, int N, int K)
{
    extern __shared__ char sm2[];
    const uint32_t sbase = smem_u32(sm2);
    const int tid = threadIdx.x, lane = tid & 31, w = tid >> 5;
    const int wm = (w >> 2) * 64, wn = (w & 3) * 32;
    const int bm = blockIdx.y * 128, bn = blockIdx.x * 128;
    const int wslot = (w & 3) * 4;

    float acc[4][4][4];
#pragma unroll
    for (int i = 0; i < 4; i++)
#pragma unroll
        for (int j = 0; j < 4; j++)
#pragma unroll
            for (int q = 0; q < 4; q++) acc[i][j][q] = 0.f;

    const int niter = K >> 5;
    const uint32_t a_lane = (uint32_t)((wm + (lane & 15)) * 80 + ((lane >> 4) << 4));

    issue_stage(sbase,        Ahi, Alo, Bhi, Blo, bm, bn, 0,  N, K, tid);
    asm volatile("cp.async.commit_group;" ::: "memory");
    issue_stage(sbase + HSTG, Ahi, Alo, Bhi, Blo, bm, bn, 32, N, K, tid);
    asm volatile("cp.async.commit_group;" ::: "memory");

    int cbuf = 0;
    int ibuf = 2;
    for (int it = 0; it < niter; ++it) {
        if (it + 2 < niter) {
            issue_stage(sbase + (uint32_t)ibuf * HSTG,
                        Ahi, Alo, Bhi, Blo, bm, bn, (it + 2) << 5, N, K, tid);
            asm volatile("cp.async.commit_group;" ::: "memory");
            asm volatile("cp.async.wait_group 2;" ::: "memory");
            if (++ibuf == 3) ibuf = 0;
        } else if (it + 1 < niter) {
            asm volatile("cp.async.wait_group 1;" ::: "memory");
        } else {
            asm volatile("cp.async.wait_group 0;" ::: "memory");
        }
        __syncthreads();

        const uint32_t sA   = sbase + (uint32_t)cbuf * HSTG;
        const uint32_t sAlo = sA + 10240;
        const uint32_t sB   = sA + 20480;
        const uint32_t sBlo = sB + 8192;

#pragma unroll
        for (int ks = 0; ks < 32; ks += 16) {
            const int klane = ks + (lane & 15);
            const uint32_t bro = (uint32_t)(klane * 256);
            uint32_t bh[4][2], bl[4][2];
#pragma unroll
            for (int ni = 0; ni < 4; ni++) {
                const int slot = wslot + ni;
                const uint32_t off = bro + (uint32_t)((((slot ^ klane) & 7) | (slot & 8)) * 16);
                ldmx2t(bh[ni], sB + off);
                ldmx2t(bl[ni], sBlo + off);
            }
            const uint32_t ao = a_lane + ks * 2;
#pragma unroll
            for (int mi = 0; mi < 4; mi++) {
                uint32_t ah[4], al_[4];
                ldmx4(ah,  sA   + ao + mi * (16 * 80));
                ldmx4(al_, sAlo + ao + mi * (16 * 80));
#pragma unroll
                for (int ni = 0; ni < 4; ni++) {
                    mma16816(acc[mi][ni], ah,  bh[ni]);
                    mma16816(acc[mi][ni], al_, bh[ni]);
                    mma16816(acc[mi][ni], ah,  bl[ni]);
                }
            }
        }
        __syncthreads();
        if (++cbuf == 3) cbuf = 0;
    }

    // epilogue
#pragma unroll
    for (int mi = 0; mi < 4; mi++) {
        const int row = bm + wm + mi * 16 + (lane >> 2);
#pragma unroll
        for (int ni = 0; ni < 4; ni++) {
            const int col = bn + wn + ni * 8 + (lane & 3) * 2;
            float2 v0; v0.x = acc[mi][ni][0]; v0.y = acc[mi][ni][1];
            float2 v1; v1.x = acc[mi][ni][2]; v1.y = acc[mi][ni][3];
            *reinterpret_cast<float2*>(C + (size_t)row * N + col)       = v0;
            *reinterpret_cast<float2*>(C + (size_t)(row + 8) * N + col) = v1;
        }
    }
}

// ================= ALL convolutions in ONE launch =================
#define CONV_QK_BLOCKS (RROWS * 18)
#define CONV_V_BLOCKS  ((RROWS * VAL_DIM * 2) / 256)
__global__ __launch_bounds__(256) void conv_all(
    const float* __restrict__ Z, const float* __restrict__ qcw,
    const float* __restrict__ kcw, const float* __restrict__ vcw,
    float* __restrict__ qn, float* __restrict__ kn0, float* __restrict__ kn1,
    float* __restrict__ vs0, float* __restrict__ vs1)
{
    const int bid = blockIdx.x, tid = threadIdx.x;
    if (bid < CONV_QK_BLOCKS) {
        const int r = bid / 18, u = bid - (bid / 18) * 18;
        const int tsel = u / 6, h = u - tsel * 6;
        const int zoff = tsel * KEY_DIM;
        const float* W = (tsel == 0) ? qcw : kcw + (size_t)(tsel - 1) * (KEY_DIM * 4);
        const float outscale = (tsel == 0) ? 0.0625f : 1.f;
        float* Out = (tsel == 0) ? qn : ((tsel == 1) ? kn0 : kn1);

        const int b = r >> 10, t = r & 1023;
        const int c = h * DK + tid;
        float acc = 0.f;
#pragma unroll
        for (int j = 0; j < 4; j++) {
            int tj = t - 3 + j;
            if (tj >= 0) acc = fmaf(Z[(size_t)(b * TLEN + tj) * PROJ_W + zoff + c], W[c * 4 + j], acc);
        }
        float y = acc / (1.f + expf(-acc));
        __shared__ float sred[256];
        sred[tid] = y * y;
        __syncthreads();
        for (int s = 128; s > 0; s >>= 1) {
            if (tid < s) sred[tid] += sred[tid + s];
            __syncthreads();
        }
        float scale = rsqrtf(sred[0] + 1e-12f) * outscale;
        Out[(size_t)r * KEY_DIM + c] = y * scale;
    } else {
        int idx = (bid - CONV_QK_BLOCKS) * 256 + tid;
        const int vsel = (idx >= RROWS * VAL_DIM) ? 1 : 0;
        idx -= vsel * (RROWS * VAL_DIM);
        const int zoff = OFF_V0 + vsel * VAL_DIM;
        const float* W = vcw + (size_t)vsel * (VAL_DIM * 4);
        float* Out = vsel ? vs1 : vs0;

        const int c = idx % VAL_DIM;
        const int r = idx / VAL_DIM;
        const int b = r >> 10, t = r & 1023;
        float acc = 0.f;
#pragma unroll
        for (int j = 0; j < 4; j++) {
            int tj = t - 3 + j;
            if (tj >= 0) acc = fmaf(Z[(size_t)(b * TLEN + tj) * PROJ_W + zoff + c], W[c * 4 + j], acc);
        }
        Out[idx] = acc / (1.f + expf(-acc));
    }
}

// ---------------- packed f32x2 helpers ----------------
union F2U { float2 f; unsigned long long u; };

__device__ __forceinline__ F2U ffma2(F2U a, F2U b, F2U c) {
    F2U r;
    asm("fma.rn.f32x2 %0, %1, %2, %3;" : "=l"(r.u) : "l"(a.u), "l"(b.u), "l"(c.u));
    return r;
}
__device__ __forceinline__ F2U fmul2(F2U a, F2U b) {
    F2U r;
    asm("mul.rn.f32x2 %0, %1, %2;" : "=l"(r.u) : "l"(a.u), "l"(b.u));
    return r;
}

// ---------------- gated delta-rule recurrence v4: cp.async ring + hoisted scalars ----------------
// Same fused telescoped math as v3 (verified passing), but:
//  * k0/k1/q staged global->smem via a 4-deep cp.async ring (no register staging chain)
//  * decay=exp(g), beta0, beta1 for ALL 1024 steps precomputed into smem once
//  * one __syncthreads per step; barrier separates compute(t-1) from reuse-issue
// 128 threads = 4 warps; half-warp owns 2 columns. grid (12, 32).
#define RPF 4   // ring stages
__global__ void __launch_bounds__(128, 3) delta_recur4(
    const float* __restrict__ Qn,  const float* __restrict__ Kn0, const float* __restrict__ Kn1,
    const float* __restrict__ Vs0, const float* __restrict__ Vs1,
    const float* __restrict__ Be0, const float* __restrict__ Be1,
    const float* __restrict__ Gd,  float* __restrict__ O)
{
    const int bh = blockIdx.x;
    const int b = bh / HH, h = bh % HH;
    const int tid = threadIdx.x;
    const int lane = tid & 31, w = tid >> 5;
    const int half = lane >> 4, l0 = lane & 15;
    const int col0 = blockIdx.y * 16 + w * 4 + half * 2;

    __shared__ __align__(16) float skr[RPF][3][256];  // ring: [stage][k0,k1,q][dim]
    __shared__ float sdec[TLEN], sb0[TLEN], sb1[TLEN];

    const uint32_t ring_base = smem_u32(&skr[0][0][0]);

    // ---- hoist all per-step scalars (decay/beta) into smem ----
    for (int i = tid; i < TLEN; i += 128) {
        const int gi = (b * TLEN + i) * HH + h;
        sdec[i] = expf(Gd[gi]);
        sb0[i] = Be0[gi];
        sb1[i] = Be1[gi];
    }

    // ---- cp.async stage issuer: 192 chunks of 16B (3 arrays x 1KB) ----
    const float* kbase0 = Kn0 + (size_t)(b * TLEN) * KEY_DIM + h * DK;
    const float* kbase1 = Kn1 + (size_t)(b * TLEN) * KEY_DIM + h * DK;
    const float* qbase  = Qn  + (size_t)(b * TLEN) * KEY_DIM + h * DK;
#define ISSUE_STAGE_T(tt) do { \
        const uint32_t sdst = ring_base + (uint32_t)(((tt) & (RPF - 1)) * 3072); \
        const size_t roff = (size_t)(tt) * KEY_DIM; \
        int cid = tid; \
        { int arr = cid >> 6, off = (cid & 63) << 4; \
          const float* src = (arr == 0 ? kbase0 : (arr == 1 ? kbase1 : qbase)) + roff + (off >> 2); \
          cpa16(sdst + arr * 1024 + off, src); } \
        cid = tid + 128; \
        if (cid < 192) { int arr = cid >> 6, off = (cid & 63) << 4; \
          const float* src = (arr == 0 ? kbase0 : (arr == 1 ? kbase1 : qbase)) + roff + (off >> 2); \
          cpa16(sdst + arr * 1024 + off, src); } \
        asm volatile("cp.async.commit_group;" ::: "memory"); \
    } while (0)

    // prologue: 3 stages in flight
    ISSUE_STAGE_T(0);
    ISSUE_STAGE_T(1);
    ISSUE_STAGE_T(2);

    // v for t=0 (register path, independent)
    const size_t vb0 = (size_t)(b * TLEN) * VAL_DIM + h * DV + col0;
    float2 vc0 = *reinterpret_cast<const float2*>(Vs0 + vb0);
    float2 vc1 = *reinterpret_cast<const float2*>(Vs1 + vb0);

    F2U S0[8], S1[8];
#pragma unroll
    for (int j = 0; j < 8; j++) { S0[j].u = 0ull; S1[j].u = 0ull; }

    for (int t = 0; t < TLEN; t++) {
        // wait for stage t (exact tail handling)
        if (t + 2 < TLEN)      asm volatile("cp.async.wait_group 2;" ::: "memory");
        else if (t + 1 < TLEN) asm volatile("cp.async.wait_group 1;" ::: "memory");
        else                   asm volatile("cp.async.wait_group 0;" ::: "memory");
        __syncthreads();   // stage-t data visible; all compute(t-1) done -> safe to reuse buffer

        if (t + 3 < TLEN) ISSUE_STAGE_T(t + 3);

        // prefetch v(t+1) (independent registers)
        float2 vn0, vn1;
        const bool more = (t + 1 < TLEN);
        if (more) {
            const size_t vb = (size_t)(b * TLEN + t + 1) * VAL_DIM + h * DV + col0;
            vn0 = *reinterpret_cast<const float2*>(Vs0 + vb);
            vn1 = *reinterpret_cast<const float2*>(Vs1 + vb);
        }

        const float decay = sdec[t];
        const float b0cur = sb0[t], b1cur = sb1[t];
        const int buf = t & (RPF - 1);
        const float2* pk0 = reinterpret_cast<const float2*>(skr[buf][0]);
        const float2* pk1 = reinterpret_cast<const float2*>(skr[buf][1]);
        const float2* pq  = reinterpret_cast<const float2*>(skr[buf][2]);

        // ---- load k0, k1, q slices ----
        F2U rk0[8], rk1[8], rq[8];
#pragma unroll
        for (int j = 0; j < 8; j++) {
            rk0[j].f = pk0[j * 16 + l0];
            rk1[j].f = pk1[j * 16 + l0];
            rq [j].f = pq [j * 16 + l0];
        }

        // ---- fused dots: 6 column dots + 3 scalar dots ----
        F2U a00, a01, a10, a11, aq0, aq1, c01, cq0, cq1;
        a00.u=0; a01.u=0; a10.u=0; a11.u=0; aq0.u=0; aq1.u=0; c01.u=0; cq0.u=0; cq1.u=0;
#pragma unroll
        for (int j = 0; j < 8; j++) {
            a00 = ffma2(rk0[j], S0[j], a00);
            a01 = ffma2(rk0[j], S1[j], a01);
            a10 = ffma2(rk1[j], S0[j], a10);
            a11 = ffma2(rk1[j], S1[j], a11);
            aq0 = ffma2(rq[j],  S0[j], aq0);
            aq1 = ffma2(rq[j],  S1[j], aq1);
            c01 = ffma2(rk0[j], rk1[j], c01);
            cq0 = ffma2(rq[j],  rk0[j], cq0);
            cq1 = ffma2(rq[j],  rk1[j], cq1);
        }
        float d00 = a00.f.x + a00.f.y, d01 = a01.f.x + a01.f.y;
        float d10 = a10.f.x + a10.f.y, d11 = a11.f.x + a11.f.y;
        float dq0 = aq0.f.x + aq0.f.y, dq1 = aq1.f.x + aq1.f.y;
        float s01 = c01.f.x + c01.f.y, sq0 = cq0.f.x + cq0.f.y, sq1 = cq1.f.x + cq1.f.y;

        // ---- ONE shfl reduction phase (9 values, depth 4) ----
#pragma unroll
        for (int m = 8; m > 0; m >>= 1) {
            d00 += __shfl_xor_sync(0xffffffffu, d00, m);
            d01 += __shfl_xor_sync(0xffffffffu, d01, m);
            d10 += __shfl_xor_sync(0xffffffffu, d10, m);
            d11 += __shfl_xor_sync(0xffffffffu, d11, m);
            dq0 += __shfl_xor_sync(0xffffffffu, dq0, m);
            dq1 += __shfl_xor_sync(0xffffffffu, dq1, m);
            s01 += __shfl_xor_sync(0xffffffffu, s01, m);
            sq0 += __shfl_xor_sync(0xffffffffu, sq0, m);
            sq1 += __shfl_xor_sync(0xffffffffu, sq1, m);
        }

        // ---- scalar math ----
        const float u0A = (vc0.x - decay * d00) * b0cur;
        const float u0B = (vc0.y - decay * d01) * b0cur;
        const float u1A = (vc1.x - decay * d10 - s01 * u0A) * b1cur;
        const float u1B = (vc1.y - decay * d11 - s01 * u0B) * b1cur;
        if (l0 == 0) {
            float2 ov;
            ov.x = decay * dq0 + sq0 * u0A + sq1 * u1A;
            ov.y = decay * dq1 + sq0 * u0B + sq1 * u1B;
            *reinterpret_cast<float2*>(O + (size_t)((b * TLEN + t) * HH + h) * DV + col0) = ov;
        }

        // ---- fused update: S = decay*S + k0 u0 + k1 u1 ----
        F2U dec2; dec2.f = make_float2(decay, decay);
        F2U u0Av; u0Av.f = make_float2(u0A, u0A);
        F2U u0Bv; u0Bv.f = make_float2(u0B, u0B);
        F2U u1Av; u1Av.f = make_float2(u1A, u1A);
        F2U u1Bv; u1Bv.f = make_float2(u1B, u1B);
#pragma unroll
        for (int j = 0; j < 8; j++) {
            S0[j] = ffma2(S0[j], dec2, ffma2(rk0[j], u0Av, fmul2(rk1[j], u1Av)));
            S1[j] = ffma2(S1[j], dec2, ffma2(rk0[j], u0Bv, fmul2(rk1[j], u1Bv)));
        }

        if (more) { vc0 = vn0; vc1 = vn1; }
    }
#undef ISSUE_STAGE_T
}

// ---------------- RMS norm over DV + gated SiLU -> bf16 hi/lo ----------------
__global__ __launch_bounds__(256) void rms_gate(
    const float* __restrict__ Ob, const float* __restrict__ Gx,
    const float* __restrict__ onw,
    __nv_bfloat16* __restrict__ Yh, __nv_bfloat16* __restrict__ Yl)
{
    const int r = blockIdx.x, h = blockIdx.y, tid = threadIdx.x;
    const size_t base = (size_t)(r * HH + h) * DV;
    const size_t gbase = (size_t)r * PROJ_W + OFF_G + h * DV;
    float o0 = Ob[base + tid], o1 = Ob[base + tid + 256];
    __shared__ float sred[256];
    sred[tid] = o0 * o0 + o1 * o1;
    __syncthreads();
    for (int s = 128; s > 0; s >>= 1) {
        if (tid < s) sred[tid] += sred[tid + s];
        __syncthreads();
    }
    float scale = rsqrtf(sred[0] * (1.f / 512.f) + 1e-5f);
    float g0 = Gx[gbase + tid], g1 = Gx[gbase + tid + 256];
    float y0 = o0 * scale * onw[tid]       * (g0 / (1.f + expf(-g0)));
    float y1 = o1 * scale * onw[tid + 256] * (g1 / (1.f + expf(-g1)));
    __nv_bfloat16 h0 = __float2bfloat16_rn(y0);
    __nv_bfloat16 h1 = __float2bfloat16_rn(y1);
    Yh[base + tid]       = h0;
    Yh[base + tid + 256] = h1;
    Yl[base + tid]       = __float2bfloat16_rn(y0 - __bfloat162float(h0));
    Yl[base + tid + 256] = __float2bfloat16_rn(y1 - __bfloat162float(h1));
}

// ---------------- launch ----------------
extern "C" void kernel_launch(void* const* d_in, const int* in_sizes, int n_in,
                              void* d_out, int out_size)
{
    const float* x     = (const float*)d_in[0];
    const float* q_w   = (const float*)d_in[1];
    const float* k_ws  = (const float*)d_in[2];
    const float* v_ws  = (const float*)d_in[3];
    const float* b_ws  = (const float*)d_in[4];
    const float* a_w   = (const float*)d_in[5];
    const float* g_w   = (const float*)d_in[6];
    const float* o_w   = (const float*)d_in[7];
    const float* qcw   = (const float*)d_in[8];
    const float* kcw   = (const float*)d_in[9];
    const float* vcw   = (const float*)d_in[10];
    const float* A_log = (const float*)d_in[11];
    const float* dtb   = (const float*)d_in[12];
    const float* onw   = (const float*)d_in[13];
    float* out = (float*)d_out;

    float *proj, *qn, *kn0, *kn1, *vs0, *vs1, *ob;
    float *be0, *be1, *gd;
    __nv_bfloat16 *xhi, *xlo, *wch, *wcl, *owh, *owl, *ybh, *ybl;
    cudaGetSymbolAddress((void**)&proj, g_proj);
    cudaGetSymbolAddress((void**)&xhi, g_xhi);
    cudaGetSymbolAddress((void**)&xlo, g_xlo);
    cudaGetSymbolAddress((void**)&wch, g_wch);
    cudaGetSymbolAddress((void**)&wcl, g_wcl);
    cudaGetSymbolAddress((void**)&owh, g_owh);
    cudaGetSymbolAddress((void**)&owl, g_owl);
    cudaGetSymbolAddress((void**)&ybh, g_ybh);
    cudaGetSymbolAddress((void**)&ybl, g_ybl);
    cudaGetSymbolAddress((void**)&qn,  g_qn);
    cudaGetSymbolAddress((void**)&kn0, g_kn0);
    cudaGetSymbolAddress((void**)&kn1, g_kn1);
    cudaGetSymbolAddress((void**)&vs0, g_vs0);
    cudaGetSymbolAddress((void**)&vs1, g_vs1);
    cudaGetSymbolAddress((void**)&ob,  g_ob);
    cudaGetSymbolAddress((void**)&be0, g_be0);
    cudaGetSymbolAddress((void**)&be1, g_be1);
    cudaGetSymbolAddress((void**)&gd,  g_gd);

    cudaFuncSetAttribute(hgemm2, cudaFuncAttributeMaxDynamicSharedMemorySize, HSM3);

    // 1) input split
    {
        int n = RROWS * HID;
        cvt_split<<<(n/4 + 255)/256, 256>>>(x, xhi, xlo, n);
    }
    // 2) all weight splits (single launch)
    cvt_w_all<<<CVTW_BLOCKS, 256>>>(q_w, k_ws, v_ws, g_w, o_w, wch, wcl, owh, owl);

    // 3) fused tiny projections + activations
    gemm18b<<<RROWS / 2, 128>>>(x, b_ws, a_w, A_log, dtb, be0, be1, gd);

    // 4) merged projection GEMM   (launch #4 -> ncu capture target)
    hgemm2<<<dim3(PROJ_W/128, RROWS/128), 256, HSM3>>>(xhi, xlo, wch, wcl, proj, RROWS, PROJ_W, HID);

    // 5) all convs (single launch)
    conv_all<<<CONV_QK_BLOCKS + CONV_V_BLOCKS, 256>>>(proj, qcw, kcw, vcw, qn, kn0, kn1, vs0, vs1);

    // 6) sequential gated delta rule (cp.async-staged fused formulation)
    delta_recur4<<<dim3(BSZ * HH, DV / 16), 128>>>(qn, kn0, kn1, vs0, vs1, be0, be1, gd, ob);

    // 7) output norm + gate (emits bf16 hi/lo)
    rms_gate<<<dim3(RROWS, HH), 256>>>(ob, proj, onw, ybh, ybl);

    // 8) final projection
    hgemm2<<<dim3(HID/128, RROWS/128), 256, HSM3>>>(ybh, ybl, owh, owl, out, RROWS, HID, VAL_DIM);
}